// round 15
// baseline (speedup 1.0000x reference)
#include <cuda_runtime.h>
#include <cstdint>

// Shapes (fixed per reference setup_inputs)
#define C_  256
#define OUT_PER_B (1 << 22)              // 128*128*256 floats per output batch
#define IN_PER_B  (1 << 20)              // 64*64*256 elements per input batch

#define BLOCKS   1024
#define THREADS  256
#define NTHREADS (BLOCKS * THREADS)      // 262,144 = groups in ONE input batch /1

#define ZTILE_BYTES 16384                // smem TMA source tile

// Graded chunks (batches): [1, 2,2,2,2,2,2,2, 1]  -> small exposed edges.
// Kernel i scatters chunk i and TMA-zeros chunk i+1's region.

__device__ __forceinline__ uint32_t smem_u32(const void* p) {
    uint32_t a;
    asm("{ .reg .u64 t; cvta.to.shared.u64 t, %1; cvt.u32.u64 %0, t; }"
        : "=r"(a) : "l"(p));
    return a;
}

// ZPB = zero tiles per block (1 tile = 16 KB). Region bytes = ZPB * BLOCKS * 16K.
template <int ZPB>
__device__ __forceinline__ void tma_zero_slice(char* region, uint32_t zsrc) {
    asm volatile("fence.proxy.async.shared::cta;" ::: "memory");
#pragma unroll
    for (int j = 0; j < ZPB; j++) {
        char* dst = region + (size_t)(blockIdx.x + j * BLOCKS) * ZTILE_BYTES;
        asm volatile("cp.async.bulk.global.shared::cta.bulk_group [%0], [%1], %2;"
                     :: "l"(dst), "r"(zsrc), "n"(ZTILE_BYTES) : "memory");
    }
    asm volatile("cp.async.bulk.commit_group;" ::: "memory");
    asm volatile("cp.async.bulk.wait_group 0;" ::: "memory");
}

// Prime: zero chunk 0's region (1 batch = 16.8 MB -> 1 tile/block).
__global__ void __launch_bounds__(THREADS) prime_zero_kernel(float* __restrict__ out) {
    __shared__ __align__(128) float4 zbuf[ZTILE_BYTES / 16];
    float4 z = make_float4(0.f, 0.f, 0.f, 0.f);
#pragma unroll
    for (int j = 0; j < 4; j++)
        zbuf[threadIdx.x + j * THREADS] = z;
    __syncthreads();
    if (threadIdx.x == 0)
        tma_zero_slice<1>((char*)out, smem_u32(zbuf));
}

// GPT groups of 4 elements per thread; ZPB zero-tiles per block for next chunk.
template <int GPT, int ZPB>
__global__ void __launch_bounds__(THREADS) fused_scatter_kernel(
        const float4* __restrict__ updates4,
        const int4*   __restrict__ mask4,
        float*        __restrict__ out,
        int   gbase,                      // first group of this chunk
        float* zregion) {                 // next chunk's region (unused if ZPB==0)
    __shared__ __align__(128) float4 zbuf[ZTILE_BYTES / 16];

    int tid = blockIdx.x * blockDim.x + threadIdx.x;

    // front-batched input loads (exact fit: all GPT groups valid)
    int4   m[GPT];
    float4 u[GPT];
#pragma unroll
    for (int k = 0; k < GPT; k++) {
        int g = gbase + tid + k * NTHREADS;
        m[k] = mask4[g];
        u[k] = updates4[g];
    }

    // warp 0 owns the zero tile + TMA issue; other warps never block
    if (ZPB > 0 && threadIdx.x < 32) {
        float4 z = make_float4(0.f, 0.f, 0.f, 0.f);
#pragma unroll
        for (int j = 0; j < 32; j++)            // 32 lanes * 32 float4 = 16 KB
            zbuf[threadIdx.x + j * 32] = z;
        __syncwarp();
        if (threadIdx.x == 0)
            tma_zero_slice<ZPB>((char*)zregion, smem_u32(zbuf));
    }

    // dest = out + b*OUT_PER_B + (mask & ~(C-1)) + channel(lane)
#pragma unroll
    for (int k = 0; k < GPT; k++) {
        int e0 = (gbase + tid + k * NTHREADS) << 2;
        float* ob = out + ((size_t)(e0 >> 20) << 22) + (e0 & (C_ - 1));
        atomicAdd(ob + (m[k].x & ~(C_ - 1)) + 0, u[k].x);
        atomicAdd(ob + (m[k].y & ~(C_ - 1)) + 1, u[k].y);
        atomicAdd(ob + (m[k].z & ~(C_ - 1)) + 2, u[k].z);
        atomicAdd(ob + (m[k].w & ~(C_ - 1)) + 3, u[k].w);
    }
}

extern "C" void kernel_launch(void* const* d_in, const int* in_sizes, int n_in,
                              void* d_out, int out_size) {
    const float4* updates4 = (const float4*)d_in[0];
    const int4*   mask4    = (const int4*)d_in[1];
    float*        out      = (float*)d_out;

    // chunk batch sizes: [1, 2*7, 1]; group base advances by batches*262144;
    // region base advances by batches*OUT_PER_B.
    prime_zero_kernel<<<BLOCKS, THREADS>>>(out);

    int    gbase = 0;
    size_t rbase = 0;                              // region offset in floats

    // chunk 0: 1 batch, zeros chunk 1 (2 batches)
    fused_scatter_kernel<1, 2><<<BLOCKS, THREADS>>>(
        updates4, mask4, out, gbase, out + (rbase + OUT_PER_B));
    gbase += NTHREADS;            // 1 batch of groups
    rbase += OUT_PER_B;

    // chunks 1..6: 2 batches each, zero next 2-batch chunk
    for (int i = 1; i <= 6; i++) {
        fused_scatter_kernel<2, 2><<<BLOCKS, THREADS>>>(
            updates4, mask4, out, gbase, out + (rbase + 2 * (size_t)OUT_PER_B));
        gbase += 2 * NTHREADS;
        rbase += 2 * (size_t)OUT_PER_B;
    }

    // chunk 7: 2 batches, zeros chunk 8 (1 batch)
    fused_scatter_kernel<2, 1><<<BLOCKS, THREADS>>>(
        updates4, mask4, out, gbase, out + (rbase + 2 * (size_t)OUT_PER_B));
    gbase += 2 * NTHREADS;
    rbase += 2 * (size_t)OUT_PER_B;

    // chunk 8: 1 batch, no zero duty — small exposed tail
    fused_scatter_kernel<1, 0><<<BLOCKS, THREADS>>>(
        updates4, mask4, out, gbase, nullptr);
}

// round 16
// speedup vs baseline: 1.1377x; 1.1377x over previous
#include <cuda_runtime.h>
#include <cstdint>

// Shapes (fixed per reference setup_inputs)
#define C_  256
#define OUT_PER_B (1 << 22)              // 128*128*256
#define IN_PER_B  (1 << 20)              // 64*64*256

#define NCHUNK           8
#define CHUNK_OUT_F      (2 * OUT_PER_B)             // 8,388,608 floats (2 batches)
#define CHUNK_OUT_BYTES  (CHUNK_OUT_F * 4)           // 33,554,432 B
#define CHUNK_GROUPS     ((2 * IN_PER_B) / 4)        // 524,288 groups of 4

// Exact fit: 1024 blocks * 256 threads * 2 groups == 524,288
#define BLOCKS   1024
#define THREADS  256
#define NTHREADS (BLOCKS * THREADS)                  // 262,144

#define ZTILE_BYTES       16384
#define ZTILES_PER_CHUNK  (CHUNK_OUT_BYTES / ZTILE_BYTES)   // 2048 (2 per block)

__device__ __forceinline__ uint32_t smem_u32(const void* p) {
    uint32_t a;
    asm("{ .reg .u64 t; cvta.to.shared.u64 t, %1; cvt.u32.u64 %0, t; }"
        : "=r"(a) : "l"(p));
    return a;
}

__device__ __forceinline__ void tma_zero_slice(char* region, uint32_t zsrc) {
    asm volatile("fence.proxy.async.shared::cta;" ::: "memory");
#pragma unroll
    for (int j = 0; j < ZTILES_PER_CHUNK / BLOCKS; j++) {
        char* dst = region + (size_t)(blockIdx.x + j * BLOCKS) * ZTILE_BYTES;
        asm volatile("cp.async.bulk.global.shared::cta.bulk_group [%0], [%1], %2;"
                     :: "l"(dst), "r"(zsrc), "n"(ZTILE_BYTES) : "memory");
    }
    asm volatile("cp.async.bulk.commit_group;" ::: "memory");
    asm volatile("cp.async.bulk.wait_group 0;" ::: "memory");
}

__global__ void __launch_bounds__(THREADS) prime_zero_kernel(float* __restrict__ out) {
    __shared__ __align__(128) float4 zbuf[ZTILE_BYTES / 16];
    float4 z = make_float4(0.f, 0.f, 0.f, 0.f);
#pragma unroll
    for (int j = 0; j < 4; j++)
        zbuf[threadIdx.x + j * THREADS] = z;
    __syncthreads();
    if (threadIdx.x == 0)
        tma_zero_slice((char*)out, smem_u32(zbuf));
}

// R13-proven chunk kernel (launched for c = 0..6; always has zero duty)
__global__ void __launch_bounds__(THREADS) fused_scatter_kernel(
        const float4* __restrict__ updates4,
        const int4*   __restrict__ mask4,
        float*        __restrict__ out,
        int chunk) {
    __shared__ __align__(128) float4 zbuf[ZTILE_BYTES / 16];

    int tid = blockIdx.x * blockDim.x + threadIdx.x;

    int g0 = chunk * CHUNK_GROUPS + tid;
    int g1 = g0 + NTHREADS;                // always valid (exact fit)

    int4   ma = mask4[g0];
    float4 ua = updates4[g0];
    int4   mb = mask4[g1];
    float4 ub = updates4[g1];

    // warp 0 owns the zero tile + TMA issue; other warps never block
    if (threadIdx.x < 32 && chunk + 1 < NCHUNK) {
        float4 z = make_float4(0.f, 0.f, 0.f, 0.f);
#pragma unroll
        for (int j = 0; j < 32; j++)            // 32 lanes * 32 float4 = 16 KB
            zbuf[threadIdx.x + j * 32] = z;
        __syncwarp();
        if (threadIdx.x == 0)
            tma_zero_slice((char*)(out + (size_t)(chunk + 1) * CHUNK_OUT_F),
                           smem_u32(zbuf));
    }

    int e0a = g0 << 2;
    int e0b = g1 << 2;
    float* oa = out + ((size_t)(e0a >> 20) << 22) + (e0a & (C_ - 1));
    float* ob = out + ((size_t)(e0b >> 20) << 22) + (e0b & (C_ - 1));

    atomicAdd(oa + (ma.x & ~(C_ - 1)) + 0, ua.x);
    atomicAdd(oa + (ma.y & ~(C_ - 1)) + 1, ua.y);
    atomicAdd(oa + (ma.z & ~(C_ - 1)) + 2, ua.z);
    atomicAdd(oa + (ma.w & ~(C_ - 1)) + 3, ua.w);
    atomicAdd(ob + (mb.x & ~(C_ - 1)) + 0, ub.x);
    atomicAdd(ob + (mb.y & ~(C_ - 1)) + 1, ub.y);
    atomicAdd(ob + (mb.z & ~(C_ - 1)) + 2, ub.z);
    atomicAdd(ob + (mb.w & ~(C_ - 1)) + 3, ub.w);
}

// Tail: scatter ONE batch (1 group/thread, no smem, no zero duty).
__global__ void __launch_bounds__(THREADS) tail_scatter_kernel(
        const float4* __restrict__ updates4,
        const int4*   __restrict__ mask4,
        float*        __restrict__ out,
        int gbase) {
    int tid = blockIdx.x * blockDim.x + threadIdx.x;
    int g = gbase + tid;                   // exact fit: 1 batch = NTHREADS groups

    int4   m = mask4[g];
    float4 u = updates4[g];

    int e0 = g << 2;
    float* ob = out + ((size_t)(e0 >> 20) << 22) + (e0 & (C_ - 1));
    atomicAdd(ob + (m.x & ~(C_ - 1)) + 0, u.x);
    atomicAdd(ob + (m.y & ~(C_ - 1)) + 1, u.y);
    atomicAdd(ob + (m.z & ~(C_ - 1)) + 2, u.z);
    atomicAdd(ob + (m.w & ~(C_ - 1)) + 3, u.w);
}

extern "C" void kernel_launch(void* const* d_in, const int* in_sizes, int n_in,
                              void* d_out, int out_size) {
    const float4* updates4 = (const float4*)d_in[0];
    const int4*   mask4    = (const int4*)d_in[1];
    float*        out      = (float*)d_out;

    prime_zero_kernel<<<BLOCKS, THREADS>>>(out);

    // interior: identical to R13 for c = 0..6 (kernel 6 zeros chunk 7)
    for (int c = 0; c < NCHUNK - 1; c++) {
        fused_scatter_kernel<<<BLOCKS, THREADS>>>(updates4, mask4, out, c);
    }

    // chunk 7 (batches 14,15): two 1-batch tails — halves the exposed drain
    int gbase = (NCHUNK - 1) * CHUNK_GROUPS;           // 7 * 524,288
    tail_scatter_kernel<<<BLOCKS, THREADS>>>(updates4, mask4, out, gbase);
    tail_scatter_kernel<<<BLOCKS, THREADS>>>(updates4, mask4, out, gbase + NTHREADS);
}